// round 2
// baseline (speedup 1.0000x reference)
#include <cuda_runtime.h>
#include <math.h>

#define Bc    4
#define Tt    2048
#define TRAIN 1536
#define Dd    512
#define Hh    8
#define DHd   64
#define Ll    12
#define FFd   2048
#define Vv    100
#define BT    (Bc*Tt)
#define TEST  (Tt-TRAIN)
#define MTEST (Bc*TEST)

// ---------------- scratch (static device globals; no allocations) ----------------
__device__ float g_rep [BT*Dd];          // residual stream
__device__ float g_h   [BT*Dd];          // LN output
__device__ float g_qkv [BT*3*Dd];        // fused qkv
__device__ float g_attn[BT*Dd];          // attention output
__device__ float g_ff  [BT*FFd];         // FF hidden
__device__ float g_test[MTEST*Dd];       // head input
__device__ float g_phid[MTEST*2*Dd];     // head hidden
__device__ float g_cos [Tt*32];
__device__ float g_sin [Tt*32];

// ---------------- helpers ----------------
__device__ __forceinline__ float gelu_f(float x){
    float x3 = x*x*x;
    return 0.5f*x*(1.f + tanhf(0.7978845608028654f*(x + 0.044715f*x3)));
}

// ---------------- embedding add ----------------
__global__ void embed_kernel(const float* __restrict__ R, const int* __restrict__ y,
                             const float* __restrict__ emb){
    int row = blockIdx.x;           // b*T + t
    int t = row & (Tt-1);
    int b = row >> 11;
    const float4* Rr = (const float4*)(R + (size_t)row*Dd);
    float4* Or = (float4*)(g_rep + (size_t)row*Dd);
    if (t < TRAIN){
        int yv = y[b*TRAIN + t];
        const float4* E = (const float4*)(emb + (size_t)yv*Dd);
        for (int i = threadIdx.x; i < Dd/4; i += blockDim.x){
            float4 a = Rr[i]; float4 e = E[i];
            a.x += e.x; a.y += e.y; a.z += e.z; a.w += e.w;
            Or[i] = a;
        }
    } else {
        for (int i = threadIdx.x; i < Dd/4; i += blockDim.x) Or[i] = Rr[i];
    }
}

// ---------------- layernorm (one block per row, 128 threads) ----------------
__global__ void ln_kernel(const float* __restrict__ x, const float* __restrict__ g,
                          const float* __restrict__ be, float* __restrict__ out){
    __shared__ float sh[Dd];
    __shared__ float red[4];
    int row = blockIdx.x;
    const float* xr = x + (size_t)row*Dd;
    float s = 0.f;
    for (int i = threadIdx.x; i < Dd; i += 128){ float v = xr[i]; sh[i] = v; s += v; }
    #pragma unroll
    for (int o = 16; o; o >>= 1) s += __shfl_xor_sync(0xffffffffu, s, o);
    if ((threadIdx.x & 31) == 0) red[threadIdx.x >> 5] = s;
    __syncthreads();
    float mu = (red[0]+red[1]+red[2]+red[3]) * (1.f/Dd);
    float vs = 0.f;
    for (int i = threadIdx.x; i < Dd; i += 128){ float d = sh[i]-mu; vs += d*d; }
    #pragma unroll
    for (int o = 16; o; o >>= 1) vs += __shfl_xor_sync(0xffffffffu, vs, o);
    __syncthreads();
    if ((threadIdx.x & 31) == 0) red[threadIdx.x >> 5] = vs;
    __syncthreads();
    float var = (red[0]+red[1]+red[2]+red[3]) * (1.f/Dd);
    float rs = rsqrtf(var + 1e-5f);
    float* orow = out + (size_t)row*Dd;
    for (int i = threadIdx.x; i < Dd; i += 128)
        orow[i] = (sh[i]-mu)*rs*g[i] + be[i];
}

// ---------------- RoPE table (matches JAX fp32 op sequence) ----------------
__global__ void rope_table_kernel(){
    int t = blockIdx.x, i = threadIdx.x;   // i in 0..31
    float inv = (float)pow(100000.0, -((double)(2*i))/64.0);
    float ang = (float)t * inv;
    g_cos[t*32+i] = cosf(ang);
    g_sin[t*32+i] = sinf(ang);
}

// ---------------- RoPE apply (interleaved) on q and k in g_qkv ----------------
__global__ void rope_apply_kernel(){
    int row = blockIdx.x;              // b*T + t
    int t = row & (Tt-1);
    int h = threadIdx.x >> 5;          // 0..7
    int i = threadIdx.x & 31;          // 0..31
    float c = g_cos[t*32+i], s = g_sin[t*32+i];
    size_t base = (size_t)row*(3*Dd) + h*DHd + 2*i;
    float q1 = g_qkv[base], q2 = g_qkv[base+1];
    g_qkv[base]   = q1*c - q2*s;
    g_qkv[base+1] = q1*s + q2*c;
    size_t kb = base + Dd;
    float k1 = g_qkv[kb], k2 = g_qkv[kb+1];
    g_qkv[kb]   = k1*c - k2*s;
    g_qkv[kb+1] = k1*s + k2*c;
}

// ---------------- flash attention ----------------
// mask: allowed = (s < TRAIN) || (s == t). So: loop keys 0..TRAIN-1, then one
// self-key fixup for t >= TRAIN. Online softmax, fp32 throughout.
// grid: (T/16, H, B), block 256 = 8 warps, each warp handles 2 query rows.
__global__ __launch_bounds__(256) void attn_kernel(){
    const int b = blockIdx.z, h = blockIdx.y;
    const int t0 = blockIdx.x * 16;
    const int warp = threadIdx.x >> 5, lane = threadIdx.x & 31;
    const float SCALE = 0.125f; // 1/sqrt(64)

    __shared__ float Qs[16][64];
    __shared__ float Ks[64][65];
    __shared__ float Vs[64][65];
    __shared__ float Ps[16][64];

    const size_t rstride = 3*Dd;
    // load 16 query rows
    for (int idx = threadIdx.x; idx < 16*64; idx += 256){
        int r = idx >> 6, d = idx & 63;
        Qs[r][d] = g_qkv[(size_t)(b*Tt + t0 + r)*rstride + h*DHd + d];
    }
    __syncthreads();

    float m[2]  = {-INFINITY, -INFINITY};
    float lsum[2] = {0.f, 0.f};
    float o[2][2] = {{0.f,0.f},{0.f,0.f}};    // dims: lane, lane+32

    for (int s0 = 0; s0 < TRAIN; s0 += 64){
        for (int idx = threadIdx.x; idx < 64*64; idx += 256){
            int s = idx >> 6, d = idx & 63;
            size_t base = (size_t)(b*Tt + s0 + s)*rstride + h*DHd + d;
            Ks[s][d] = g_qkv[base + Dd];
            Vs[s][d] = g_qkv[base + 2*Dd];
        }
        __syncthreads();
        #pragma unroll
        for (int r = 0; r < 2; r++){
            int row = warp*2 + r;
            float sc0 = 0.f, sc1 = 0.f;
            #pragma unroll 16
            for (int d = 0; d < 64; d++){
                float q = Qs[row][d];
                sc0 += q * Ks[lane][d];
                sc1 += q * Ks[lane+32][d];
            }
            sc0 *= SCALE; sc1 *= SCALE;
            float tmax = fmaxf(sc0, sc1);
            #pragma unroll
            for (int off = 16; off; off >>= 1)
                tmax = fmaxf(tmax, __shfl_xor_sync(0xffffffffu, tmax, off));
            float mnew = fmaxf(m[r], tmax);
            float alpha = expf(m[r] - mnew);
            float p0 = expf(sc0 - mnew), p1 = expf(sc1 - mnew);
            float psum = p0 + p1;
            #pragma unroll
            for (int off = 16; off; off >>= 1)
                psum += __shfl_xor_sync(0xffffffffu, psum, off);
            lsum[r] = lsum[r]*alpha + psum;
            o[r][0] *= alpha; o[r][1] *= alpha;
            m[r] = mnew;
            Ps[row][lane] = p0; Ps[row][lane+32] = p1;
            __syncwarp();
            #pragma unroll 16
            for (int kk = 0; kk < 64; kk++){
                float p = Ps[row][kk];
                o[r][0] += p * Vs[kk][lane];
                o[r][1] += p * Vs[kk][lane+32];
            }
            __syncwarp();
        }
        __syncthreads();
    }

    // self-key fixup + writeback
    #pragma unroll
    for (int r = 0; r < 2; r++){
        int row = warp*2 + r;
        int t = t0 + row;
        if (t >= TRAIN){
            size_t base = (size_t)(b*Tt + t)*rstride + h*DHd;
            float part = Qs[row][lane]    * g_qkv[base + Dd + lane]
                       + Qs[row][lane+32] * g_qkv[base + Dd + lane + 32];
            #pragma unroll
            for (int off = 16; off; off >>= 1)
                part += __shfl_xor_sync(0xffffffffu, part, off);
            float sv = part * SCALE;
            float mnew = fmaxf(m[r], sv);
            float alpha = expf(m[r] - mnew);
            float p = expf(sv - mnew);
            lsum[r] = lsum[r]*alpha + p;
            o[r][0] = o[r][0]*alpha + p * g_qkv[base + 2*Dd + lane];
            o[r][1] = o[r][1]*alpha + p * g_qkv[base + 2*Dd + lane + 32];
            m[r] = mnew;
        }
        float inv = 1.f / lsum[r];
        size_t orow = (size_t)(b*Tt + t)*Dd + h*DHd;
        g_attn[orow + lane]      = o[r][0]*inv;
        g_attn[orow + lane + 32] = o[r][1]*inv;
    }
}

// ---------------- tiled fp32 GEMM: C = epilogue(A[M,K] @ Bw[K,N] + bias) ----------------
// EPI: 0 = +bias, 1 = gelu(+bias), 2 = res + (+bias)
template<int EPI>
__global__ __launch_bounds__(256) void gemm_kernel(
    const float* __restrict__ A, const float* __restrict__ Bw,
    const float* __restrict__ bias, const float* res,
    float* C, int M, int N, int K)
{
    __shared__ __align__(16) float As[16][64];   // [k][m]
    __shared__ __align__(16) float Bs[16][64];   // [k][n]
    const int tid = threadIdx.x;
    const int m0 = blockIdx.y * 64, n0 = blockIdx.x * 64;
    const int ty = tid >> 4, tx = tid & 15;      // microtile coords

    const int arow = tid >> 2;                   // 0..63
    const int acol = (tid & 3) * 4;              // 0..12
    const int brow = tid >> 4;                   // 0..15
    const int bcol = (tid & 15) * 4;             // 0..60

    const float* Aptr = A + (size_t)(m0 + arow)*K + acol;
    float acc[4][4] = {};

    for (int k0 = 0; k0 < K; k0 += 16){
        float4 av = *(const float4*)(Aptr + k0);
        As[acol+0][arow] = av.x;
        As[acol+1][arow] = av.y;
        As[acol+2][arow] = av.z;
        As[acol+3][arow] = av.w;
        float4 bv;
        if (n0 + bcol < N)
            bv = *(const float4*)(Bw + (size_t)(k0 + brow)*N + n0 + bcol);
        else
            bv = make_float4(0.f,0.f,0.f,0.f);
        *(float4*)&Bs[brow][bcol] = bv;
        __syncthreads();
        #pragma unroll
        for (int kk = 0; kk < 16; kk++){
            float4 a = *(const float4*)&As[kk][ty*4];
            float4 bb = *(const float4*)&Bs[kk][tx*4];
            float ar[4] = {a.x, a.y, a.z, a.w};
            float br[4] = {bb.x, bb.y, bb.z, bb.w};
            #pragma unroll
            for (int i = 0; i < 4; i++)
                #pragma unroll
                for (int j = 0; j < 4; j++)
                    acc[i][j] += ar[i]*br[j];
        }
        __syncthreads();
    }

    #pragma unroll
    for (int i = 0; i < 4; i++){
        int mm = m0 + ty*4 + i;
        #pragma unroll
        for (int j = 0; j < 4; j++){
            int nn = n0 + tx*4 + j;
            if (nn < N){
                float v = acc[i][j] + bias[nn];
                if (EPI == 1) v = gelu_f(v);
                if (EPI == 2) v += res[(size_t)mm*N + nn];
                C[(size_t)mm*N + nn] = v;
            }
        }
    }
}

// ---------------- extract test rows ----------------
__global__ void extract_kernel(){
    int r = blockIdx.x;                  // 0..MTEST-1
    int b = r >> 9, i = r & 511;
    const float4* src = (const float4*)(g_rep + (size_t)(b*Tt + TRAIN + i)*Dd);
    float4* dst = (float4*)(g_test + (size_t)r*Dd);
    for (int j = threadIdx.x; j < Dd/4; j += blockDim.x) dst[j] = src[j];
}

// ---------------- launcher ----------------
extern "C" void kernel_launch(void* const* d_in, const int* in_sizes, int n_in,
                              void* d_out, int out_size){
    const float* R    = (const float*)d_in[0];
    const int*   y    = (const int*)  d_in[1];
    const float* emb  = (const float*)d_in[2];
    const float* Wqkv = (const float*)d_in[3];
    const float* bqkv = (const float*)d_in[4];
    const float* Wo   = (const float*)d_in[5];
    const float* bo   = (const float*)d_in[6];
    const float* ln1g = (const float*)d_in[7];
    const float* ln1b = (const float*)d_in[8];
    const float* ln2g = (const float*)d_in[9];
    const float* ln2b = (const float*)d_in[10];
    const float* W1   = (const float*)d_in[11];
    const float* b1   = (const float*)d_in[12];
    const float* W2   = (const float*)d_in[13];
    const float* b2   = (const float*)d_in[14];
    const float* pW1  = (const float*)d_in[15];
    const float* pb1  = (const float*)d_in[16];
    const float* pW2  = (const float*)d_in[17];
    const float* pb2  = (const float*)d_in[18];

    float *rep, *h, *qkv, *attn, *ff, *test, *phid;
    cudaGetSymbolAddress((void**)&rep,  g_rep);
    cudaGetSymbolAddress((void**)&h,    g_h);
    cudaGetSymbolAddress((void**)&qkv,  g_qkv);
    cudaGetSymbolAddress((void**)&attn, g_attn);
    cudaGetSymbolAddress((void**)&ff,   g_ff);
    cudaGetSymbolAddress((void**)&test, g_test);
    cudaGetSymbolAddress((void**)&phid, g_phid);

    rope_table_kernel<<<Tt, 32>>>();
    embed_kernel<<<BT, 128>>>(R, y, emb);

    for (int l = 0; l < Ll; l++){
        ln_kernel<<<BT, 128>>>(rep, ln1g + l*Dd, ln1b + l*Dd, h);
        gemm_kernel<0><<<dim3(24, 128), 256>>>(h, Wqkv + (size_t)l*Dd*3*Dd,
                                               bqkv + (size_t)l*3*Dd, nullptr, qkv,
                                               BT, 3*Dd, Dd);
        rope_apply_kernel<<<BT, 256>>>();
        attn_kernel<<<dim3(Tt/16, Hh, Bc), 256>>>();
        gemm_kernel<2><<<dim3(8, 128), 256>>>(attn, Wo + (size_t)l*Dd*Dd,
                                              bo + (size_t)l*Dd, rep, rep,
                                              BT, Dd, Dd);
        ln_kernel<<<BT, 128>>>(rep, ln2g + l*Dd, ln2b + l*Dd, h);
        gemm_kernel<1><<<dim3(32, 128), 256>>>(h, W1 + (size_t)l*Dd*FFd,
                                               b1 + (size_t)l*FFd, nullptr, ff,
                                               BT, FFd, Dd);
        gemm_kernel<2><<<dim3(8, 128), 256>>>(ff, W2 + (size_t)l*FFd*Dd,
                                              b2 + (size_t)l*Dd, rep, rep,
                                              BT, Dd, FFd);
    }

    extract_kernel<<<MTEST, 128>>>();
    gemm_kernel<1><<<dim3(16, MTEST/64), 256>>>(test, pW1, pb1, nullptr, phid,
                                                MTEST, 2*Dd, Dd);
    gemm_kernel<0><<<dim3(2, MTEST/64), 256>>>(phid, pW2, pb2, nullptr,
                                               (float*)d_out, MTEST, Vv, 2*Dd);
}

// round 4
// speedup vs baseline: 2.7045x; 2.7045x over previous
#include <cuda_runtime.h>
#include <cuda_bf16.h>
#include <math.h>
#include <stdint.h>

#define Bc    4
#define Tt    2048
#define TRAIN 1536
#define Dd    512
#define Ll    12
#define FFd   2048
#define BT    (Bc*Tt)
#define NBH   32
#define MTEST 2048

typedef __nv_bfloat16 bf16;

// ---------------- static buffers ----------------
__device__ float g_rep [BT*Dd];
__device__ float g_qkv [BT*3*Dd];
__device__ float g_S   [(size_t)NBH*Tt*TRAIN];
__device__ bf16  g_Ph  [(size_t)NBH*Tt*TRAIN];
__device__ bf16  g_Pl  [(size_t)NBH*Tt*TRAIN];
__device__ float g_O   [(size_t)NBH*Tt*64];
__device__ float g_pd  [NBH*Tt];
__device__ bf16  g_hh[BT*Dd], g_hl[BT*Dd];
__device__ bf16  g_ah[BT*Dd], g_al[BT*Dd];
__device__ bf16  g_fh[BT*FFd], g_fl[BT*FFd];
__device__ bf16  g_qh[NBH*Tt*64], g_ql[NBH*Tt*64];
__device__ bf16  g_kh[NBH*Tt*64], g_kl[NBH*Tt*64];
__device__ bf16  g_Vth[(size_t)NBH*128*Tt], g_Vtl[(size_t)NBH*128*Tt];
__device__ bf16  g_th[MTEST*Dd], g_tl[MTEST*Dd];
__device__ bf16  g_gh[MTEST*2*Dd], g_gl[MTEST*2*Dd];
__device__ bf16  g_Wqkvh[Ll*3*Dd*Dd], g_Wqkvl[Ll*3*Dd*Dd];
__device__ bf16  g_Woh[Ll*Dd*Dd],  g_Wol[Ll*Dd*Dd];
__device__ bf16  g_W1h[Ll*FFd*Dd], g_W1l[Ll*FFd*Dd];
__device__ bf16  g_W2h[Ll*Dd*FFd], g_W2l[Ll*Dd*FFd];
__device__ bf16  g_pW1h[2*Dd*Dd],  g_pW1l[2*Dd*Dd];
__device__ bf16  g_pW2h[128*2*Dd], g_pW2l[128*2*Dd];
__device__ float g_cos[Tt*32], g_sin[Tt*32];

// ---------------- helpers ----------------
__device__ __forceinline__ float gelu_f(float x){
    float x3 = x*x*x;
    return 0.5f*x*(1.f + tanhf(0.7978845608028654f*(x + 0.044715f*x3)));
}
__device__ __forceinline__ void split2(float x, bf16& h, bf16& l){
    h = __float2bfloat16(x);
    l = __float2bfloat16(x - __bfloat162float(h));
}
__device__ __forceinline__ uint32_t smem_u32(const void* p){
    uint32_t a;
    asm("{ .reg .u64 t; cvta.to.shared.u64 t, %1; cvt.u32.u64 %0, t; }" : "=r"(a) : "l"(p));
    return a;
}
__device__ __forceinline__ void cpasync16(uint32_t dst, const void* src){
    asm volatile("cp.async.cg.shared.global [%0], [%1], 16;" :: "r"(dst), "l"(src) : "memory");
}
__device__ __forceinline__ void ldsm4(uint32_t* r, uint32_t a){
    asm volatile("ldmatrix.sync.aligned.m8n8.x4.shared.b16 {%0,%1,%2,%3}, [%4];"
        : "=r"(r[0]),"=r"(r[1]),"=r"(r[2]),"=r"(r[3]) : "r"(a));
}
__device__ __forceinline__ void ldsm2(uint32_t* r, uint32_t a){
    asm volatile("ldmatrix.sync.aligned.m8n8.x2.shared.b16 {%0,%1}, [%2];"
        : "=r"(r[0]),"=r"(r[1]) : "r"(a));
}
__device__ __forceinline__ void mma16816(float* c, const uint32_t* a, const uint32_t* b){
    asm volatile("mma.sync.aligned.m16n8k16.row.col.f32.bf16.bf16.f32 "
        "{%0,%1,%2,%3}, {%4,%5,%6,%7}, {%8,%9}, {%0,%1,%2,%3};"
        : "+f"(c[0]),"+f"(c[1]),"+f"(c[2]),"+f"(c[3])
        : "r"(a[0]),"r"(a[1]),"r"(a[2]),"r"(a[3]), "r"(b[0]),"r"(b[1]));
}

// ---------------- split-bf16 HMMA GEMM ----------------
// C[M,N] = A[M,K] @ B[N,K]^T ; 3-term split; batched via blockIdx.z.
#define BK 32
#define LDS 40
#define TILE_B (128*LDS*2)
#define STAGE_B (4*TILE_B)
#define GSM (2*STAGE_B)

__global__ __launch_bounds__(256) void mma_gemm(
    const bf16* __restrict__ Ah, const bf16* __restrict__ Al,
    const bf16* __restrict__ Bh, const bf16* __restrict__ Bl,
    const float* __restrict__ bias, const float* __restrict__ res,
    float* C, bf16* Chi, bf16* Clo,
    int K, int ldb, int Nreal, int ldC, size_t sA, size_t sB, size_t sC, int EPI)
{
    extern __shared__ __align__(128) char smem[];
    const uint32_t sb = smem_u32(smem);
    const int tid = threadIdx.x, lane = tid & 31, wid = tid >> 5;
    const int m0 = blockIdx.y*128, n0 = blockIdx.x*128;
    const size_t zb = blockIdx.z;
    const bf16* pAh = Ah + zb*sA + (size_t)m0*K;
    const bf16* pAl = Al + zb*sA + (size_t)m0*K;
    const bf16* pBh = Bh + zb*sB + (size_t)n0*ldb;
    const bf16* pBl = Bl + zb*sB + (size_t)n0*ldb;

    const int row2 = tid >> 1;                 // 0..127 (2 segs/thread/tile half)
    const int sA0 = (tid & 1)*2;               // segment pair base

    float acc[4][4][4] = {};
    const int nk = K/BK;

    // -------- async tile loader: chunk c -> stage s --------
    auto issue = [&](int c, int s){
        uint32_t base = sb + s*STAGE_B;
        #pragma unroll
        for (int i = 0; i < 2; i++){
            int seg = tid + i*256;             // 0..511
            int row = seg >> 2, s4 = seg & 3;
            uint32_t doff = (uint32_t)(row*LDS + s4*8)*2;
            const size_t go = (size_t)row*K + c*BK + s4*8;
            const size_t gob = (size_t)row*ldb + c*BK + s4*8;
            cpasync16(base + 0*TILE_B + doff, pAh + go);
            cpasync16(base + 1*TILE_B + doff, pAl + go);
            cpasync16(base + 2*TILE_B + doff, pBh + gob);
            cpasync16(base + 3*TILE_B + doff, pBl + gob);
        }
        asm volatile("cp.async.commit_group;" ::: "memory");
    };

    issue(0, 0);
    const int wm = (wid>>2)*64, wn = (wid&3)*32;
    const int aRow = lane & 15, aCol = (lane >> 4)*8;
    const int bRow = lane & 7,  bCol = ((lane >> 3)&1)*8;

    for (int c = 0; c < nk; c++){
        int s = c & 1;
        if (c+1 < nk){
            issue(c+1, s^1);
            asm volatile("cp.async.wait_group 1;" ::: "memory");
        } else {
            asm volatile("cp.async.wait_group 0;" ::: "memory");
        }
        __syncthreads();
        uint32_t base = sb + s*STAGE_B;
        #pragma unroll
        for (int ks = 0; ks < 2; ks++){
            uint32_t a_h[4][4], a_l[4][4], b_h[4][2], b_l[4][2];
            #pragma unroll
            for (int mt = 0; mt < 4; mt++){
                uint32_t ad = base + (uint32_t)((wm + mt*16 + aRow)*LDS + ks*16 + aCol)*2;
                ldsm4(a_h[mt], ad);
                ldsm4(a_l[mt], ad + TILE_B);
            }
            #pragma unroll
            for (int nt = 0; nt < 4; nt++){
                uint32_t bd = base + 2*TILE_B + (uint32_t)((wn + nt*8 + bRow)*LDS + ks*16 + bCol)*2;
                ldsm2(b_h[nt], bd);
                ldsm2(b_l[nt], bd + TILE_B);
            }
            #pragma unroll
            for (int mt = 0; mt < 4; mt++)
                #pragma unroll
                for (int nt = 0; nt < 4; nt++){
                    mma16816(acc[mt][nt], a_h[mt], b_h[nt]);
                    mma16816(acc[mt][nt], a_h[mt], b_l[nt]);
                    mma16816(acc[mt][nt], a_l[mt], b_h[nt]);
                }
        }
        __syncthreads();
    }

    // -------- epilogue --------
    const int r0 = lane >> 2, cW = (lane & 3)*2;
    #pragma unroll
    for (int mt = 0; mt < 4; mt++)
    #pragma unroll
    for (int h = 0; h < 2; h++){
        int gm = m0 + wm + mt*16 + r0 + h*8;
        #pragma unroll
        for (int nt = 0; nt < 4; nt++){
            float v0 = acc[mt][nt][h*2+0], v1 = acc[mt][nt][h*2+1];
            int gn = n0 + wn + nt*8 + cW;
            size_t off = zb*sC + (size_t)gm*ldC + gn;
            if (bias){ v0 += __ldg(bias+gn); v1 += __ldg(bias+gn+1); }
            if (EPI == 1){
                split2(gelu_f(v0), Chi[off],   Clo[off]);
                split2(gelu_f(v1), Chi[off+1], Clo[off+1]);
            } else {
                if (res){ v0 += res[off]; v1 += res[off+1]; }
                if (gn   < Nreal) C[off]   = v0;
                if (gn+1 < Nreal) C[off+1] = v1;
            }
        }
    }
    (void)row2; (void)sA0;
}

// ---------------- weight transpose + split: W[K,N] -> out[Npad][K] ----------------
__global__ void wsplit_kernel(const float* __restrict__ W, bf16* oh, bf16* ol,
                              int K, int N, int Npad){
    __shared__ float sm[32][33];
    int n0 = blockIdx.x*32, k0 = blockIdx.y*32, z = blockIdx.z;
    const float* Wb = W + (size_t)z*K*N;
    size_t ob = (size_t)z*Npad*K;
    int tx = threadIdx.x, ty = threadIdx.y;
    #pragma unroll
    for (int j = 0; j < 4; j++){
        int n = n0 + tx;
        sm[ty+8*j][tx] = (n < N) ? Wb[(size_t)(k0+ty+8*j)*N + n] : 0.f;
    }
    __syncthreads();
    #pragma unroll
    for (int j = 0; j < 4; j++){
        size_t o = ob + (size_t)(n0+ty+8*j)*K + k0 + tx;
        split2(sm[tx][ty+8*j], oh[o], ol[o]);
    }
}

// ---------------- misc kernels ----------------
__global__ void embed_kernel(const float* __restrict__ R, const int* __restrict__ y,
                             const float* __restrict__ emb){
    int row = blockIdx.x, t = row & (Tt-1), b = row >> 11;
    const float4* Rr = (const float4*)(R + (size_t)row*Dd);
    float4* Or = (float4*)(g_rep + (size_t)row*Dd);
    if (t < TRAIN){
        int yv = y[b*TRAIN + t];
        const float4* E = (const float4*)(emb + (size_t)yv*Dd);
        for (int i = threadIdx.x; i < Dd/4; i += blockDim.x){
            float4 a = Rr[i]; float4 e = E[i];
            a.x += e.x; a.y += e.y; a.z += e.z; a.w += e.w;
            Or[i] = a;
        }
    } else {
        for (int i = threadIdx.x; i < Dd/4; i += blockDim.x) Or[i] = Rr[i];
    }
}

__global__ void ln_kernel(const float* __restrict__ g, const float* __restrict__ be){
    __shared__ float sh[Dd];
    __shared__ float red[4];
    int row = blockIdx.x;
    const float* xr = g_rep + (size_t)row*Dd;
    float s = 0.f;
    for (int i = threadIdx.x; i < Dd; i += 128){ float v = xr[i]; sh[i] = v; s += v; }
    #pragma unroll
    for (int o = 16; o; o >>= 1) s += __shfl_xor_sync(~0u, s, o);
    if ((threadIdx.x & 31) == 0) red[threadIdx.x >> 5] = s;
    __syncthreads();
    float mu = (red[0]+red[1]+red[2]+red[3]) * (1.f/Dd);
    float vs = 0.f;
    for (int i = threadIdx.x; i < Dd; i += 128){ float d = sh[i]-mu; vs += d*d; }
    #pragma unroll
    for (int o = 16; o; o >>= 1) vs += __shfl_xor_sync(~0u, vs, o);
    __syncthreads();
    if ((threadIdx.x & 31) == 0) red[threadIdx.x >> 5] = vs;
    __syncthreads();
    float rs = rsqrtf((red[0]+red[1]+red[2]+red[3])*(1.f/Dd) + 1e-5f);
    for (int i = threadIdx.x; i < Dd; i += 128){
        size_t o = (size_t)row*Dd + i;
        split2((sh[i]-mu)*rs*g[i] + be[i], g_hh[o], g_hl[o]);
    }
}

__global__ void rope_table_kernel(){
    int t = blockIdx.x, i = threadIdx.x;
    float inv = (float)pow(100000.0, -((double)(2*i))/64.0);
    float ang = (float)t * inv;
    g_cos[t*32+i] = cosf(ang);
    g_sin[t*32+i] = sinf(ang);
}

__global__ void rope_scatter_kernel(){
    int row = blockIdx.x, t = row & (Tt-1), b = row >> 11;
    int j = threadIdx.x, h = j >> 5, i = j & 31;
    float c = g_cos[t*32+i], s = g_sin[t*32+i];
    size_t qb = (size_t)row*1536 + h*64 + 2*i;
    float q1 = g_qkv[qb], q2 = g_qkv[qb+1];
    float r1 = (q1*c - q2*s)*0.125f, r2 = (q1*s + q2*c)*0.125f;
    g_qkv[qb] = r1; g_qkv[qb+1] = r2;
    size_t qo = ((size_t)(b*8+h)*Tt + t)*64 + 2*i;
    split2(r1, g_qh[qo], g_ql[qo]); split2(r2, g_qh[qo+1], g_ql[qo+1]);
    float k1 = g_qkv[qb+512], k2 = g_qkv[qb+513];
    float s1 = k1*c - k2*s, s2 = k1*s + k2*c;
    g_qkv[qb+512] = s1; g_qkv[qb+513] = s2;
    split2(s1, g_kh[qo], g_kl[qo]); split2(s2, g_kh[qo+1], g_kl[qo+1]);
    #pragma unroll
    for (int r = 0; r < 2; r++){
        int d = j + 256*r, h2 = d >> 6, dd = d & 63;
        float v = g_qkv[(size_t)row*1536 + 1024 + d];
        size_t vo = ((size_t)(b*8+h2)*128 + dd)*Tt + t;
        split2(v, g_Vth[vo], g_Vtl[vo]);
    }
}

__global__ __launch_bounds__(256) void softmax_kernel(){
    int t = blockIdx.x, bh = blockIdx.y, tid = threadIdx.x;
    __shared__ float red[8], shv;
    size_t rb = ((size_t)bh*Tt + t)*TRAIN;
    if (t >= TRAIN && tid < 32){
        size_t qb = ((size_t)(bh>>3)*Tt + t)*1536 + (bh&7)*64;
        float p = g_qkv[qb+tid]*g_qkv[qb+512+tid] + g_qkv[qb+32+tid]*g_qkv[qb+544+tid];
        #pragma unroll
        for (int o = 16; o; o >>= 1) p += __shfl_xor_sync(~0u, p, o);
        if (tid == 0) shv = p;
    }
    if (tid == 0 && t < TRAIN) shv = -INFINITY;
    __syncthreads();
    float sv = shv;
    float vals[6]; float m = sv;
    #pragma unroll
    for (int k = 0; k < 6; k++){ vals[k] = g_S[rb + tid + 256*k]; m = fmaxf(m, vals[k]); }
    #pragma unroll
    for (int o = 16; o; o >>= 1) m = fmaxf(m, __shfl_xor_sync(~0u, m, o));
    if ((tid & 31) == 0) red[tid >> 5] = m;
    __syncthreads();
    m = red[0];
    #pragma unroll
    for (int w = 1; w < 8; w++) m = fmaxf(m, red[w]);
    float l = 0.f;
    #pragma unroll
    for (int k = 0; k < 6; k++){ vals[k] = __expf(vals[k] - m); l += vals[k]; }
    #pragma unroll
    for (int o = 16; o; o >>= 1) l += __shfl_xor_sync(~0u, l, o);
    __syncthreads();
    if ((tid & 31) == 0) red[tid >> 5] = l;
    __syncthreads();
    l = red[0]+red[1]+red[2]+red[3]+red[4]+red[5]+red[6]+red[7];
    float es = (t >= TRAIN) ? __expf(sv - m) : 0.f;
    float inv = 1.f / (l + es);
    #pragma unroll
    for (int k = 0; k < 6; k++){
        float p = vals[k]*inv;
        split2(p, g_Ph[rb + tid + 256*k], g_Pl[rb + tid + 256*k]);
    }
    if (tid == 0) g_pd[(size_t)bh*Tt + t] = es*inv;
}

__global__ void gather_kernel(){
    int row = blockIdx.x, t = row & (Tt-1), b = row >> 11;
    for (int j = threadIdx.x; j < 512; j += 256){
        int h = j >> 6, bh = b*8 + h;
        float v = g_O[((size_t)bh*Tt + t)*64 + (j & 63)];
        float pd = g_pd[(size_t)bh*Tt + t];
        if (pd != 0.f) v += pd * g_qkv[(size_t)row*1536 + 1024 + j];
        size_t o = (size_t)row*Dd + j;
        split2(v, g_ah[o], g_al[o]);
    }
}

__global__ void extract_kernel(){
    int r = blockIdx.x, b = r >> 9, i = r & 511;
    const float* src = g_rep + (size_t)(b*Tt + TRAIN + i)*Dd;
    for (int j = threadIdx.x; j < Dd; j += 128)
        split2(src[j], g_th[(size_t)r*Dd + j], g_tl[(size_t)r*Dd + j]);
}

// ---------------- launcher ----------------
#define SYM(p, s) cudaGetSymbolAddress((void**)&p, s)

extern "C" void kernel_launch(void* const* d_in, const int* in_sizes, int n_in,
                              void* d_out, int out_size){
    const float* R    = (const float*)d_in[0];
    const int*   y    = (const int*)  d_in[1];
    const float* emb  = (const float*)d_in[2];
    const float* Wqkv = (const float*)d_in[3];
    const float* bqkv = (const float*)d_in[4];
    const float* Wo   = (const float*)d_in[5];
    const float* bo   = (const float*)d_in[6];
    const float* ln1g = (const float*)d_in[7];
    const float* ln1b = (const float*)d_in[8];
    const float* ln2g = (const float*)d_in[9];
    const float* ln2b = (const float*)d_in[10];
    const float* W1   = (const float*)d_in[11];
    const float* b1   = (const float*)d_in[12];
    const float* W2   = (const float*)d_in[13];
    const float* b2   = (const float*)d_in[14];
    const float* pW1  = (const float*)d_in[15];
    const float* pb1  = (const float*)d_in[16];
    const float* pW2  = (const float*)d_in[17];
    const float* pb2  = (const float*)d_in[18];

    cudaFuncSetAttribute(mma_gemm, cudaFuncAttributeMaxDynamicSharedMemorySize, GSM);

    float *qkv, *S, *O, *rep;
    bf16 *hh,*hl,*ah,*al,*fh,*fl,*qh,*ql,*kh,*kl,*Vth,*Vtl,*Ph,*Pl,*th,*tl,*gh,*gl;
    bf16 *Wqkvh,*Wqkvl,*Woh,*Wol,*W1h,*W1l,*W2h,*W2l,*pW1h,*pW1l,*pW2h,*pW2l;
    SYM(qkv,g_qkv); SYM(S,g_S); SYM(O,g_O); SYM(rep,g_rep);
    SYM(hh,g_hh); SYM(hl,g_hl); SYM(ah,g_ah); SYM(al,g_al);
    SYM(fh,g_fh); SYM(fl,g_fl); SYM(qh,g_qh); SYM(ql,g_ql);
    SYM(kh,g_kh); SYM(kl,g_kl); SYM(Vth,g_Vth); SYM(Vtl,g_Vtl);
    SYM(Ph,g_Ph); SYM(Pl,g_Pl); SYM(th,g_th); SYM(tl,g_tl);
    SYM(gh,g_gh); SYM(gl,g_gl);
    SYM(Wqkvh,g_Wqkvh); SYM(Wqkvl,g_Wqkvl); SYM(Woh,g_Woh); SYM(Wol,g_Wol);
    SYM(W1h,g_W1h); SYM(W1l,g_W1l); SYM(W2h,g_W2h); SYM(W2l,g_W2l);
    SYM(pW1h,g_pW1h); SYM(pW1l,g_pW1l); SYM(pW2h,g_pW2h); SYM(pW2l,g_pW2l);

    dim3 wb(32, 8);
    wsplit_kernel<<<dim3(48,16,12), wb>>>(Wqkv, Wqkvh, Wqkvl, 512, 1536, 1536);
    wsplit_kernel<<<dim3(16,16,12), wb>>>(Wo,   Woh,   Wol,   512, 512,  512);
    wsplit_kernel<<<dim3(64,16,12), wb>>>(W1,   W1h,   W1l,   512, 2048, 2048);
    wsplit_kernel<<<dim3(16,64,12), wb>>>(W2,   W2h,   W2l,   2048,512,  512);
    wsplit_kernel<<<dim3(32,16,1),  wb>>>(pW1,  pW1h,  pW1l,  512, 1024, 1024);
    wsplit_kernel<<<dim3(4, 32,1),  wb>>>(pW2,  pW2h,  pW2l,  1024,100,  128);

    rope_table_kernel<<<Tt, 32>>>();
    embed_kernel<<<BT, 128>>>(R, y, emb);

    const size_t sQ = (size_t)Tt*64, sS = (size_t)Tt*TRAIN, sV = (size_t)128*Tt, sO = (size_t)Tt*64;
    for (int l = 0; l < Ll; l++){
        ln_kernel<<<BT, 128>>>(ln1g + l*Dd, ln1b + l*Dd);
        mma_gemm<<<dim3(12,64,1),256,GSM>>>(hh, hl, Wqkvh + (size_t)l*1536*512, Wqkvl + (size_t)l*1536*512,
            bqkv + l*1536, nullptr, qkv, nullptr, nullptr, 512, 512, 1536, 1536, 0,0,0, 0);
        rope_scatter_kernel<<<BT, 256>>>();
        mma_gemm<<<dim3(12,16,32),256,GSM>>>(qh, ql, kh, kl, nullptr, nullptr,
            S, nullptr, nullptr, 64, 64, 1536, 1536, sQ, sQ, sS, 0);
        softmax_kernel<<<dim3(Tt, NBH), 256>>>();
        mma_gemm<<<dim3(1,16,32),256,GSM>>>(Ph, Pl, Vth, Vtl, nullptr, nullptr,
            O, nullptr, nullptr, 1536, 2048, 64, 64, sS, sV, sO, 0);
        gather_kernel<<<BT, 256>>>();
        mma_gemm<<<dim3(4,64,1),256,GSM>>>(ah, al, Woh + (size_t)l*512*512, Wol + (size_t)l*512*512,
            bo + l*512, rep, rep, nullptr, nullptr, 512, 512, 512, 512, 0,0,0, 0);
        ln_kernel<<<BT, 128>>>(ln2g + l*Dd, ln2b + l*Dd);
        mma_gemm<<<dim3(16,64,1),256,GSM>>>(hh, hl, W1h + (size_t)l*2048*512, W1l + (size_t)l*2048*512,
            b1 + l*2048, nullptr, nullptr, fh, fl, 512, 512, 2048, 2048, 0,0,0, 1);
        mma_gemm<<<dim3(4,64,1),256,GSM>>>(fh, fl, W2h + (size_t)l*512*2048, W2l + (size_t)l*512*2048,
            b2 + l*512, rep, rep, nullptr, nullptr, 2048, 2048, 512, 512, 0,0,0, 0);
    }

    extract_kernel<<<MTEST, 128>>>();
    mma_gemm<<<dim3(8,16,1),256,GSM>>>(th, tl, pW1h, pW1l, pb1, nullptr,
        nullptr, gh, gl, 512, 512, 1024, 1024, 0,0,0, 1);
    mma_gemm<<<dim3(1,16,1),256,GSM>>>(gh, gl, pW2h, pW2l, pb2, nullptr,
        (float*)d_out, nullptr, nullptr, 1024, 1024, 100, 100, 0,0,0, 0);
}

// round 5
// speedup vs baseline: 3.6013x; 1.3316x over previous
#include <cuda_runtime.h>
#include <cuda_bf16.h>
#include <math.h>
#include <stdint.h>

#define Bc    4
#define Tt    2048
#define TRAIN 1536
#define Dd    512
#define Ll    12
#define FFd   2048
#define BT    (Bc*Tt)
#define NBH   32
#define MTEST 2048

typedef __nv_bfloat16 bf16;

// ---------------- static buffers ----------------
__device__ float g_rep [BT*Dd];
__device__ float g_qkv [BT*3*Dd];
__device__ bf16  g_hh[BT*Dd], g_hl[BT*Dd];
__device__ bf16  g_ah[BT*Dd], g_al[BT*Dd];
__device__ bf16  g_fh[BT*FFd], g_fl[BT*FFd];
__device__ bf16  g_qh[NBH*Tt*64], g_ql[NBH*Tt*64];
__device__ bf16  g_kh[NBH*Tt*64], g_kl[NBH*Tt*64];
__device__ bf16  g_Vth[(size_t)NBH*128*Tt], g_Vtl[(size_t)NBH*128*Tt];
__device__ bf16  g_th[MTEST*Dd], g_tl[MTEST*Dd];
__device__ bf16  g_gh[MTEST*2*Dd], g_gl[MTEST*2*Dd];
__device__ bf16  g_Wqkvh[Ll*3*Dd*Dd], g_Wqkvl[Ll*3*Dd*Dd];
__device__ bf16  g_Woh[Ll*Dd*Dd],  g_Wol[Ll*Dd*Dd];
__device__ bf16  g_W1h[Ll*FFd*Dd], g_W1l[Ll*FFd*Dd];
__device__ bf16  g_W2h[Ll*Dd*FFd], g_W2l[Ll*Dd*FFd];
__device__ bf16  g_pW1h[2*Dd*Dd],  g_pW1l[2*Dd*Dd];
__device__ bf16  g_pW2h[128*2*Dd], g_pW2l[128*2*Dd];
__device__ float g_cos[Tt*32], g_sin[Tt*32];

// ---------------- helpers ----------------
__device__ __forceinline__ float gelu_f(float x){
    float x3 = x*x*x;
    return 0.5f*x*(1.f + tanhf(0.7978845608028654f*(x + 0.044715f*x3)));
}
__device__ __forceinline__ void split2(float x, bf16& h, bf16& l){
    h = __float2bfloat16(x);
    l = __float2bfloat16(x - __bfloat162float(h));
}
__device__ __forceinline__ uint32_t smem_u32(const void* p){
    uint32_t a;
    asm("{ .reg .u64 t; cvta.to.shared.u64 t, %1; cvt.u32.u64 %0, t; }" : "=r"(a) : "l"(p));
    return a;
}
__device__ __forceinline__ void cpasync16(uint32_t dst, const void* src){
    asm volatile("cp.async.cg.shared.global [%0], [%1], 16;" :: "r"(dst), "l"(src) : "memory");
}
__device__ __forceinline__ void ldsm4(uint32_t* r, uint32_t a){
    asm volatile("ldmatrix.sync.aligned.m8n8.x4.shared.b16 {%0,%1,%2,%3}, [%4];"
        : "=r"(r[0]),"=r"(r[1]),"=r"(r[2]),"=r"(r[3]) : "r"(a));
}
__device__ __forceinline__ void ldsm2(uint32_t* r, uint32_t a){
    asm volatile("ldmatrix.sync.aligned.m8n8.x2.shared.b16 {%0,%1}, [%2];"
        : "=r"(r[0]),"=r"(r[1]) : "r"(a));
}
__device__ __forceinline__ void mma16816(float* c, const uint32_t* a, const uint32_t* b){
    asm volatile("mma.sync.aligned.m16n8k16.row.col.f32.bf16.bf16.f32 "
        "{%0,%1,%2,%3}, {%4,%5,%6,%7}, {%8,%9}, {%0,%1,%2,%3};"
        : "+f"(c[0]),"+f"(c[1]),"+f"(c[2]),"+f"(c[3])
        : "r"(a[0]),"r"(a[1]),"r"(a[2]),"r"(a[3]), "r"(b[0]),"r"(b[1]));
}
__device__ __forceinline__ uint32_t packbf(float lo, float hi){
    uint32_t r;
    asm("cvt.rn.bf16x2.f32 %0, %1, %2;" : "=r"(r) : "f"(hi), "f"(lo));
    return r;
}

// ================= fused flash attention =================
// grid (16 qtiles, 32 bh), block 256. K/V tiles of 64 keys, 24 tiles (train keys),
// plus per-row self-key fixup for t >= TRAIN. Output written split-bf16 to g_ah/g_al.
#define FLDS 72
#define FTILE (64*FLDS*2)          // 9216 B
#define FQT   (128*FLDS*2)         // 18432 B
#define FSTG  (4*FTILE)            // 36864 B
#define FSM   (2*FQT + 2*FSTG)     // 110592 B

__global__ __launch_bounds__(256) void flash_kernel(){
    extern __shared__ __align__(128) char smem[];
    const uint32_t sb = smem_u32(smem);
    const int tid = threadIdx.x, lane = tid & 31, warp = tid >> 5;
    const int bh = blockIdx.y, b = bh >> 3, h = bh & 7;
    const int t0 = blockIdx.x * 128;
    const int r0 = lane >> 2, cq = lane & 3;
    const int aRow = lane & 15, aCol = (lane >> 4)*8;
    const int bRow = lane & 7,  bCol = ((lane >> 3)&1)*8;
    const uint32_t QH = sb, QL = sb + FQT, ST0 = sb + 2*FQT;

    // ---- issue Q (hi+lo) + stage 0, then commit ----
    {
        #pragma unroll
        for (int i = 0; i < 8; i++){
            int idx = tid + i*256;           // 0..2047
            int tile = idx >> 10, rem = idx & 1023;
            int row = rem >> 3, ch = rem & 7;
            const bf16* src = (tile ? g_ql : g_qh) + ((size_t)bh*Tt + t0 + row)*64 + ch*8;
            cpasync16(sb + tile*FQT + (uint32_t)(row*FLDS + ch*8)*2, src);
        }
        #pragma unroll
        for (int i = 0; i < 8; i++){
            int idx = tid + i*256;
            int tile = idx >> 9, rem = idx & 511;
            int row = rem >> 3, ch = rem & 7;
            const bf16* src;
            if (tile == 0)      src = g_kh  + ((size_t)bh*Tt + row)*64 + ch*8;
            else if (tile == 1) src = g_kl  + ((size_t)bh*Tt + row)*64 + ch*8;
            else if (tile == 2) src = g_Vth + ((size_t)bh*128 + row)*Tt + ch*8;
            else                src = g_Vtl + ((size_t)bh*128 + row)*Tt + ch*8;
            cpasync16(ST0 + tile*FTILE + (uint32_t)(row*FLDS + ch*8)*2, src);
        }
        asm volatile("cp.async.commit_group;" ::: "memory");
    }

    float o[8][4] = {};
    float m0 = -INFINITY, m1 = -INFINITY, l0 = 0.f, l1 = 0.f;
    uint32_t qfh[4][4], qfl[4][4];

    for (int kt = 0; kt < 24; kt++){
        int s = kt & 1;
        if (kt + 1 < 24){
            int s2 = s ^ 1, s0n = (kt+1)*64;
            uint32_t base = ST0 + s2*FSTG;
            #pragma unroll
            for (int i = 0; i < 8; i++){
                int idx = tid + i*256;
                int tile = idx >> 9, rem = idx & 511;
                int row = rem >> 3, ch = rem & 7;
                const bf16* src;
                if (tile == 0)      src = g_kh  + ((size_t)bh*Tt + s0n + row)*64 + ch*8;
                else if (tile == 1) src = g_kl  + ((size_t)bh*Tt + s0n + row)*64 + ch*8;
                else if (tile == 2) src = g_Vth + ((size_t)bh*128 + row)*Tt + s0n + ch*8;
                else                src = g_Vtl + ((size_t)bh*128 + row)*Tt + s0n + ch*8;
                cpasync16(base + tile*FTILE + (uint32_t)(row*FLDS + ch*8)*2, src);
            }
            asm volatile("cp.async.commit_group;" ::: "memory");
            asm volatile("cp.async.wait_group 1;" ::: "memory");
        } else {
            asm volatile("cp.async.wait_group 0;" ::: "memory");
        }
        __syncthreads();

        if (kt == 0){
            #pragma unroll
            for (int ks = 0; ks < 4; ks++){
                uint32_t ad = QH + (uint32_t)((warp*16 + aRow)*FLDS + ks*16 + aCol)*2;
                ldsm4(qfh[ks], ad);
                ldsm4(qfl[ks], ad + FQT);
            }
        }

        uint32_t KB = ST0 + s*FSTG;
        // ---- S = Q K^T (3-term split) ----
        float acc[8][4] = {};
        #pragma unroll
        for (int ks = 0; ks < 4; ks++){
            #pragma unroll
            for (int g = 0; g < 2; g++){
                uint32_t bfh[4][2], bfl[4][2];
                #pragma unroll
                for (int j = 0; j < 4; j++){
                    int nt = g*4 + j;
                    uint32_t bd = KB + (uint32_t)((nt*8 + bRow)*FLDS + ks*16 + bCol)*2;
                    ldsm2(bfh[j], bd);
                    ldsm2(bfl[j], bd + FTILE);
                }
                #pragma unroll
                for (int j = 0; j < 4; j++) mma16816(acc[g*4+j], qfh[ks], bfh[j]);
                #pragma unroll
                for (int j = 0; j < 4; j++) mma16816(acc[g*4+j], qfh[ks], bfl[j]);
                #pragma unroll
                for (int j = 0; j < 4; j++) mma16816(acc[g*4+j], qfl[ks], bfh[j]);
            }
        }

        // ---- online softmax ----
        float tm0 = -INFINITY, tm1 = -INFINITY;
        #pragma unroll
        for (int nt = 0; nt < 8; nt++){
            tm0 = fmaxf(tm0, fmaxf(acc[nt][0], acc[nt][1]));
            tm1 = fmaxf(tm1, fmaxf(acc[nt][2], acc[nt][3]));
        }
        tm0 = fmaxf(tm0, __shfl_xor_sync(~0u, tm0, 1));
        tm0 = fmaxf(tm0, __shfl_xor_sync(~0u, tm0, 2));
        tm1 = fmaxf(tm1, __shfl_xor_sync(~0u, tm1, 1));
        tm1 = fmaxf(tm1, __shfl_xor_sync(~0u, tm1, 2));
        float mn0 = fmaxf(m0, tm0), mn1 = fmaxf(m1, tm1);
        float al0 = __expf(m0 - mn0), al1 = __expf(m1 - mn1);
        float ps0 = 0.f, ps1 = 0.f;
        #pragma unroll
        for (int nt = 0; nt < 8; nt++){
            acc[nt][0] = __expf(acc[nt][0] - mn0);
            acc[nt][1] = __expf(acc[nt][1] - mn0);
            acc[nt][2] = __expf(acc[nt][2] - mn1);
            acc[nt][3] = __expf(acc[nt][3] - mn1);
            ps0 += acc[nt][0] + acc[nt][1];
            ps1 += acc[nt][2] + acc[nt][3];
        }
        ps0 += __shfl_xor_sync(~0u, ps0, 1); ps0 += __shfl_xor_sync(~0u, ps0, 2);
        ps1 += __shfl_xor_sync(~0u, ps1, 1); ps1 += __shfl_xor_sync(~0u, ps1, 2);
        l0 = l0*al0 + ps0; l1 = l1*al1 + ps1;
        m0 = mn0; m1 = mn1;
        #pragma unroll
        for (int nt = 0; nt < 8; nt++){
            o[nt][0] *= al0; o[nt][1] *= al0; o[nt][2] *= al1; o[nt][3] *= al1;
        }

        // ---- O += P V (3-term split); V^T tile in smem [dim][key] ----
        uint32_t VB = KB + 2*FTILE;
        #pragma unroll
        for (int kc = 0; kc < 4; kc++){
            uint32_t aph[4], apl[4];
            {
                float e[8] = {acc[2*kc][0], acc[2*kc][1], acc[2*kc][2], acc[2*kc][3],
                              acc[2*kc+1][0], acc[2*kc+1][1], acc[2*kc+1][2], acc[2*kc+1][3]};
                float hi[8], lo[8];
                #pragma unroll
                for (int e2 = 0; e2 < 8; e2++){
                    hi[e2] = __bfloat162float(__float2bfloat16(e[e2]));
                    lo[e2] = e[e2] - hi[e2];
                }
                aph[0] = packbf(hi[0], hi[1]); aph[1] = packbf(hi[2], hi[3]);
                aph[2] = packbf(hi[4], hi[5]); aph[3] = packbf(hi[6], hi[7]);
                apl[0] = packbf(lo[0], lo[1]); apl[1] = packbf(lo[2], lo[3]);
                apl[2] = packbf(lo[4], lo[5]); apl[3] = packbf(lo[6], lo[7]);
            }
            #pragma unroll
            for (int g = 0; g < 2; g++){
                uint32_t bfh[4][2], bfl[4][2];
                #pragma unroll
                for (int j = 0; j < 4; j++){
                    int nt = g*4 + j;
                    uint32_t bd = VB + (uint32_t)((nt*8 + bRow)*FLDS + kc*16 + bCol)*2;
                    ldsm2(bfh[j], bd);
                    ldsm2(bfl[j], bd + FTILE);
                }
                #pragma unroll
                for (int j = 0; j < 4; j++) mma16816(o[g*4+j], aph, bfh[j]);
                #pragma unroll
                for (int j = 0; j < 4; j++) mma16816(o[g*4+j], aph, bfl[j]);
                #pragma unroll
                for (int j = 0; j < 4; j++) mma16816(o[g*4+j], apl, bfh[j]);
            }
        }
        __syncthreads();
    }

    // ---- self-key fixup (rows t >= TRAIN; whole block since t0 mult of 128) ----
    if (t0 >= TRAIN){
        float mm[2] = {m0, m1}, ll[2] = {l0, l1};
        #pragma unroll
        for (int r = 0; r < 2; r++){
            int trow = t0 + warp*16 + r0 + 8*r;
            size_t qb = ((size_t)(b*Tt + trow))*1536 + h*64;
            float part = 0.f;
            #pragma unroll
            for (int d = 0; d < 16; d++)
                part += g_qkv[qb + cq*16 + d] * g_qkv[qb + 512 + cq*16 + d];
            part += __shfl_xor_sync(~0u, part, 1);
            part += __shfl_xor_sync(~0u, part, 2);
            float mn = fmaxf(mm[r], part);
            float al = __expf(mm[r] - mn);
            float p  = __expf(part - mn);
            ll[r] = ll[r]*al + p;
            const float* vs = g_qkv + qb + 1024;
            #pragma unroll
            for (int nt = 0; nt < 8; nt++){
                o[nt][2*r+0] = o[nt][2*r+0]*al + p*vs[nt*8 + 2*cq + 0];
                o[nt][2*r+1] = o[nt][2*r+1]*al + p*vs[nt*8 + 2*cq + 1];
            }
        }
        l0 = ll[0]; l1 = ll[1];
    }

    // ---- normalize + split write ----
    float inv[2] = {1.f/l0, 1.f/l1};
    #pragma unroll
    for (int r = 0; r < 2; r++){
        int trow = t0 + warp*16 + r0 + 8*r;
        size_t ob = ((size_t)(b*Tt + trow))*Dd + h*64;
        #pragma unroll
        for (int nt = 0; nt < 8; nt++){
            #pragma unroll
            for (int j = 0; j < 2; j++){
                float v = o[nt][2*r+j]*inv[r];
                size_t off = ob + nt*8 + 2*cq + j;
                split2(v, g_ah[off], g_al[off]);
            }
        }
    }
}

// ---------------- split-bf16 HMMA GEMM ----------------
#define BK 32
#define LDS 40
#define TILE_B (128*LDS*2)
#define STAGE_B (4*TILE_B)
#define GSM (2*STAGE_B)

__global__ __launch_bounds__(256) void mma_gemm(
    const bf16* __restrict__ Ah, const bf16* __restrict__ Al,
    const bf16* __restrict__ Bh, const bf16* __restrict__ Bl,
    const float* __restrict__ bias, const float* __restrict__ res,
    float* C, bf16* Chi, bf16* Clo,
    int K, int ldb, int Nreal, int ldC, size_t sA, size_t sB, size_t sC, int EPI)
{
    extern __shared__ __align__(128) char smem[];
    const uint32_t sb = smem_u32(smem);
    const int tid = threadIdx.x, lane = tid & 31, wid = tid >> 5;
    const int m0 = blockIdx.y*128, n0 = blockIdx.x*128;
    const size_t zb = blockIdx.z;
    const bf16* pAh = Ah + zb*sA + (size_t)m0*K;
    const bf16* pAl = Al + zb*sA + (size_t)m0*K;
    const bf16* pBh = Bh + zb*sB + (size_t)n0*ldb;
    const bf16* pBl = Bl + zb*sB + (size_t)n0*ldb;

    float acc[4][4][4] = {};
    const int nk = K/BK;

    auto issue = [&](int c, int s){
        uint32_t base = sb + s*STAGE_B;
        #pragma unroll
        for (int i = 0; i < 2; i++){
            int seg = tid + i*256;
            int row = seg >> 2, s4 = seg & 3;
            uint32_t doff = (uint32_t)(row*LDS + s4*8)*2;
            const size_t go = (size_t)row*K + c*BK + s4*8;
            const size_t gob = (size_t)row*ldb + c*BK + s4*8;
            cpasync16(base + 0*TILE_B + doff, pAh + go);
            cpasync16(base + 1*TILE_B + doff, pAl + go);
            cpasync16(base + 2*TILE_B + doff, pBh + gob);
            cpasync16(base + 3*TILE_B + doff, pBl + gob);
        }
        asm volatile("cp.async.commit_group;" ::: "memory");
    };

    issue(0, 0);
    const int wm = (wid>>2)*64, wn = (wid&3)*32;
    const int aRow = lane & 15, aCol = (lane >> 4)*8;
    const int bRow = lane & 7,  bCol = ((lane >> 3)&1)*8;

    for (int c = 0; c < nk; c++){
        int s = c & 1;
        if (c+1 < nk){
            issue(c+1, s^1);
            asm volatile("cp.async.wait_group 1;" ::: "memory");
        } else {
            asm volatile("cp.async.wait_group 0;" ::: "memory");
        }
        __syncthreads();
        uint32_t base = sb + s*STAGE_B;
        #pragma unroll
        for (int ks = 0; ks < 2; ks++){
            uint32_t a_h[4][4], a_l[4][4], b_h[4][2], b_l[4][2];
            #pragma unroll
            for (int mt = 0; mt < 4; mt++){
                uint32_t ad = base + (uint32_t)((wm + mt*16 + aRow)*LDS + ks*16 + aCol)*2;
                ldsm4(a_h[mt], ad);
                ldsm4(a_l[mt], ad + TILE_B);
            }
            #pragma unroll
            for (int nt = 0; nt < 4; nt++){
                uint32_t bd = base + 2*TILE_B + (uint32_t)((wn + nt*8 + bRow)*LDS + ks*16 + bCol)*2;
                ldsm2(b_h[nt], bd);
                ldsm2(b_l[nt], bd + TILE_B);
            }
            #pragma unroll
            for (int mt = 0; mt < 4; mt++)
                #pragma unroll
                for (int nt = 0; nt < 4; nt++){
                    mma16816(acc[mt][nt], a_h[mt], b_h[nt]);
                    mma16816(acc[mt][nt], a_h[mt], b_l[nt]);
                    mma16816(acc[mt][nt], a_l[mt], b_h[nt]);
                }
        }
        __syncthreads();
    }

    const int r0 = lane >> 2, cW = (lane & 3)*2;
    #pragma unroll
    for (int mt = 0; mt < 4; mt++)
    #pragma unroll
    for (int hh2 = 0; hh2 < 2; hh2++){
        int gm = m0 + wm + mt*16 + r0 + hh2*8;
        #pragma unroll
        for (int nt = 0; nt < 4; nt++){
            float v0 = acc[mt][nt][hh2*2+0], v1 = acc[mt][nt][hh2*2+1];
            int gn = n0 + wn + nt*8 + cW;
            size_t off = zb*sC + (size_t)gm*ldC + gn;
            if (bias){ v0 += __ldg(bias+gn); v1 += __ldg(bias+gn+1); }
            if (EPI == 1){
                split2(gelu_f(v0), Chi[off],   Clo[off]);
                split2(gelu_f(v1), Chi[off+1], Clo[off+1]);
            } else {
                if (res){ v0 += res[off]; v1 += res[off+1]; }
                if (gn   < Nreal) C[off]   = v0;
                if (gn+1 < Nreal) C[off+1] = v1;
            }
        }
    }
}

// ---------------- weight transpose + split ----------------
__global__ void wsplit_kernel(const float* __restrict__ W, bf16* oh, bf16* ol,
                              int K, int N, int Npad){
    __shared__ float sm[32][33];
    int n0 = blockIdx.x*32, k0 = blockIdx.y*32, z = blockIdx.z;
    const float* Wb = W + (size_t)z*K*N;
    size_t ob = (size_t)z*Npad*K;
    int tx = threadIdx.x, ty = threadIdx.y;
    #pragma unroll
    for (int j = 0; j < 4; j++){
        int n = n0 + tx;
        sm[ty+8*j][tx] = (n < N) ? Wb[(size_t)(k0+ty+8*j)*N + n] : 0.f;
    }
    __syncthreads();
    #pragma unroll
    for (int j = 0; j < 4; j++){
        size_t o = ob + (size_t)(n0+ty+8*j)*K + k0 + tx;
        split2(sm[tx][ty+8*j], oh[o], ol[o]);
    }
}

// ---------------- misc kernels ----------------
__global__ void embed_kernel(const float* __restrict__ R, const int* __restrict__ y,
                             const float* __restrict__ emb){
    int row = blockIdx.x, t = row & (Tt-1), b = row >> 11;
    const float4* Rr = (const float4*)(R + (size_t)row*Dd);
    float4* Or = (float4*)(g_rep + (size_t)row*Dd);
    if (t < TRAIN){
        int yv = y[b*TRAIN + t];
        const float4* E = (const float4*)(emb + (size_t)yv*Dd);
        for (int i = threadIdx.x; i < Dd/4; i += blockDim.x){
            float4 a = Rr[i]; float4 e = E[i];
            a.x += e.x; a.y += e.y; a.z += e.z; a.w += e.w;
            Or[i] = a;
        }
    } else {
        for (int i = threadIdx.x; i < Dd/4; i += blockDim.x) Or[i] = Rr[i];
    }
}

__global__ void ln_kernel(const float* __restrict__ g, const float* __restrict__ be){
    __shared__ float sh[Dd];
    __shared__ float red[4];
    int row = blockIdx.x;
    const float* xr = g_rep + (size_t)row*Dd;
    float s = 0.f;
    for (int i = threadIdx.x; i < Dd; i += 128){ float v = xr[i]; sh[i] = v; s += v; }
    #pragma unroll
    for (int o = 16; o; o >>= 1) s += __shfl_xor_sync(~0u, s, o);
    if ((threadIdx.x & 31) == 0) red[threadIdx.x >> 5] = s;
    __syncthreads();
    float mu = (red[0]+red[1]+red[2]+red[3]) * (1.f/Dd);
    float vs = 0.f;
    for (int i = threadIdx.x; i < Dd; i += 128){ float d = sh[i]-mu; vs += d*d; }
    #pragma unroll
    for (int o = 16; o; o >>= 1) vs += __shfl_xor_sync(~0u, vs, o);
    __syncthreads();
    if ((threadIdx.x & 31) == 0) red[threadIdx.x >> 5] = vs;
    __syncthreads();
    float rs = rsqrtf((red[0]+red[1]+red[2]+red[3])*(1.f/Dd) + 1e-5f);
    for (int i = threadIdx.x; i < Dd; i += 128){
        size_t o = (size_t)row*Dd + i;
        split2((sh[i]-mu)*rs*g[i] + be[i], g_hh[o], g_hl[o]);
    }
}

__global__ void rope_table_kernel(){
    int t = blockIdx.x, i = threadIdx.x;
    float inv = (float)pow(100000.0, -((double)(2*i))/64.0);
    float ang = (float)t * inv;
    g_cos[t*32+i] = cosf(ang);
    g_sin[t*32+i] = sinf(ang);
}

__global__ void rope_scatter_kernel(){
    int row = blockIdx.x, t = row & (Tt-1), b = row >> 11;
    int j = threadIdx.x, h = j >> 5, i = j & 31;
    float c = g_cos[t*32+i], s = g_sin[t*32+i];
    size_t qb = (size_t)row*1536 + h*64 + 2*i;
    float q1 = g_qkv[qb], q2 = g_qkv[qb+1];
    float r1 = (q1*c - q2*s)*0.125f, r2 = (q1*s + q2*c)*0.125f;
    g_qkv[qb] = r1; g_qkv[qb+1] = r2;
    size_t qo = ((size_t)(b*8+h)*Tt + t)*64 + 2*i;
    split2(r1, g_qh[qo], g_ql[qo]); split2(r2, g_qh[qo+1], g_ql[qo+1]);
    float k1 = g_qkv[qb+512], k2 = g_qkv[qb+513];
    float s1 = k1*c - k2*s, s2 = k1*s + k2*c;
    g_qkv[qb+512] = s1; g_qkv[qb+513] = s2;
    split2(s1, g_kh[qo], g_kl[qo]); split2(s2, g_kh[qo+1], g_kl[qo+1]);
    #pragma unroll
    for (int r = 0; r < 2; r++){
        int d = j + 256*r, h2 = d >> 6, dd = d & 63;
        float v = g_qkv[(size_t)row*1536 + 1024 + d];
        size_t vo = ((size_t)(b*8+h2)*128 + dd)*Tt + t;
        split2(v, g_Vth[vo], g_Vtl[vo]);
    }
}

__global__ void extract_kernel(){
    int r = blockIdx.x, b = r >> 9, i = r & 511;
    const float* src = g_rep + (size_t)(b*Tt + TRAIN + i)*Dd;
    for (int j = threadIdx.x; j < Dd; j += 128)
        split2(src[j], g_th[(size_t)r*Dd + j], g_tl[(size_t)r*Dd + j]);
}

// ---------------- launcher ----------------
#define SYM(p, s) cudaGetSymbolAddress((void**)&p, s)

extern "C" void kernel_launch(void* const* d_in, const int* in_sizes, int n_in,
                              void* d_out, int out_size){
    const float* R    = (const float*)d_in[0];
    const int*   y    = (const int*)  d_in[1];
    const float* emb  = (const float*)d_in[2];
    const float* Wqkv = (const float*)d_in[3];
    const float* bqkv = (const float*)d_in[4];
    const float* Wo   = (const float*)d_in[5];
    const float* bo   = (const float*)d_in[6];
    const float* ln1g = (const float*)d_in[7];
    const float* ln1b = (const float*)d_in[8];
    const float* ln2g = (const float*)d_in[9];
    const float* ln2b = (const float*)d_in[10];
    const float* W1   = (const float*)d_in[11];
    const float* b1   = (const float*)d_in[12];
    const float* W2   = (const float*)d_in[13];
    const float* b2   = (const float*)d_in[14];
    const float* pW1  = (const float*)d_in[15];
    const float* pb1  = (const float*)d_in[16];
    const float* pW2  = (const float*)d_in[17];
    const float* pb2  = (const float*)d_in[18];

    cudaFuncSetAttribute(mma_gemm, cudaFuncAttributeMaxDynamicSharedMemorySize, GSM);
    cudaFuncSetAttribute(flash_kernel, cudaFuncAttributeMaxDynamicSharedMemorySize, FSM);

    float *qkv, *rep;
    bf16 *hh,*hl,*ah,*al,*fh,*fl,*th,*tl,*gh,*gl;
    bf16 *Wqkvh,*Wqkvl,*Woh,*Wol,*W1h,*W1l,*W2h,*W2l,*pW1h,*pW1l,*pW2h,*pW2l;
    SYM(qkv,g_qkv); SYM(rep,g_rep);
    SYM(hh,g_hh); SYM(hl,g_hl); SYM(ah,g_ah); SYM(al,g_al);
    SYM(fh,g_fh); SYM(fl,g_fl);
    SYM(th,g_th); SYM(tl,g_tl);
    SYM(gh,g_gh); SYM(gl,g_gl);
    SYM(Wqkvh,g_Wqkvh); SYM(Wqkvl,g_Wqkvl); SYM(Woh,g_Woh); SYM(Wol,g_Wol);
    SYM(W1h,g_W1h); SYM(W1l,g_W1l); SYM(W2h,g_W2h); SYM(W2l,g_W2l);
    SYM(pW1h,g_pW1h); SYM(pW1l,g_pW1l); SYM(pW2h,g_pW2h); SYM(pW2l,g_pW2l);

    dim3 wb(32, 8);
    wsplit_kernel<<<dim3(48,16,12), wb>>>(Wqkv, Wqkvh, Wqkvl, 512, 1536, 1536);
    wsplit_kernel<<<dim3(16,16,12), wb>>>(Wo,   Woh,   Wol,   512, 512,  512);
    wsplit_kernel<<<dim3(64,16,12), wb>>>(W1,   W1h,   W1l,   512, 2048, 2048);
    wsplit_kernel<<<dim3(16,64,12), wb>>>(W2,   W2h,   W2l,   2048,512,  512);
    wsplit_kernel<<<dim3(32,16,1),  wb>>>(pW1,  pW1h,  pW1l,  512, 1024, 1024);
    wsplit_kernel<<<dim3(4, 32,1),  wb>>>(pW2,  pW2h,  pW2l,  1024,100,  128);

    rope_table_kernel<<<Tt, 32>>>();
    embed_kernel<<<BT, 128>>>(R, y, emb);

    for (int l = 0; l < Ll; l++){
        ln_kernel<<<BT, 128>>>(ln1g + l*Dd, ln1b + l*Dd);
        mma_gemm<<<dim3(12,64,1),256,GSM>>>(hh, hl, Wqkvh + (size_t)l*1536*512, Wqkvl + (size_t)l*1536*512,
            bqkv + l*1536, nullptr, qkv, nullptr, nullptr, 512, 512, 1536, 1536, 0,0,0, 0);
        rope_scatter_kernel<<<BT, 256>>>();
        flash_kernel<<<dim3(16, NBH), 256, FSM>>>();
        mma_gemm<<<dim3(4,64,1),256,GSM>>>(ah, al, Woh + (size_t)l*512*512, Wol + (size_t)l*512*512,
            bo + l*512, rep, rep, nullptr, nullptr, 512, 512, 512, 512, 0,0,0, 0);
        ln_kernel<<<BT, 128>>>(ln2g + l*Dd, ln2b + l*Dd);
        mma_gemm<<<dim3(16,64,1),256,GSM>>>(hh, hl, W1h + (size_t)l*2048*512, W1l + (size_t)l*2048*512,
            b1 + l*2048, nullptr, nullptr, fh, fl, 512, 512, 2048, 2048, 0,0,0, 1);
        mma_gemm<<<dim3(4,64,1),256,GSM>>>(fh, fl, W2h + (size_t)l*512*2048, W2l + (size_t)l*512*2048,
            b2 + l*512, rep, rep, nullptr, nullptr, 2048, 2048, 512, 512, 0,0,0, 0);
    }

    extract_kernel<<<MTEST, 128>>>();
    mma_gemm<<<dim3(8,16,1),256,GSM>>>(th, tl, pW1h, pW1l, pb1, nullptr,
        nullptr, gh, gl, 512, 512, 1024, 1024, 0,0,0, 1);
    mma_gemm<<<dim3(1,16,1),256,GSM>>>(gh, gl, pW2h, pW2l, pb2, nullptr,
        (float*)d_out, nullptr, nullptr, 1024, 1024, 100, 100, 0,0,0, 0);
}